// round 5
// baseline (speedup 1.0000x reference)
#include <cuda_runtime.h>
#include <cuda_bf16.h>
#include <math.h>

// ---------------------------------------------------------------------------
// Problem constants
// ---------------------------------------------------------------------------
#define BATCH   512
#define IMG     15
#define NPIX    (IMG*IMG)          // 225
#define CH      256
#define DIM     512
#define HEADS   8
#define DH      64
#define DEPTH   6
#define MLPD    2048
#define NCLS    16
#define NPATCH  56                 // 4*(IMG-1)
#define TOKENS  57                 // NPATCH + 1
#define ROWS    (BATCH*TOKENS)     // 29184
#define EROWS   (BATCH*NPATCH)     // 28672

// ---------------------------------------------------------------------------
// Scratch (device globals; no runtime allocation allowed)
// ---------------------------------------------------------------------------
__device__ __align__(128) float d_tok[(size_t)EROWS * CH];        //  ~29 MB
__device__ __align__(128) float d_h  [(size_t)ROWS  * DIM];       //  ~60 MB
__device__ __align__(128) float d_y  [(size_t)ROWS  * DIM];       //  ~60 MB
__device__ __align__(128) float d_qkv[(size_t)ROWS  * 3*DIM];     // ~179 MB
__device__ __align__(128) float d_att[(size_t)ROWS  * DIM];       //  ~60 MB
__device__ __align__(128) float d_mlp[(size_t)ROWS  * MLPD];      // ~239 MB
__device__ __align__(128) float d_pos[TOKENS * DIM];
__device__ short g_tgt[224], g_s1[224], g_s2[224];

// ---------------------------------------------------------------------------
// Ring-table init (exact replica of reference _ring traversal)
// ---------------------------------------------------------------------------
__global__ void init_tables_kernel() {
    if (threadIdx.x != 0 || blockIdx.x != 0) return;
    int n = 0;
    for (int i = 1; i <= 7; i++) {
        int a1 = 7 - i, a2 = 7 + i, b1 = 7 - i, b2 = 7 + i;
        int d0 = 0, d1 = 1, l1 = a1, l2 = b1 - 1, start = 0;
        while (true) {
            l1 += d0; l2 += d1;
            if (l1 == a1 && l2 == b1) { if (start) break; start = 1; }
            if (l1 > a2)      { d0 = 0;  d1 = -1; l1 -= 1; continue; }
            else if (l2 < b1) { d0 = -1; d1 = 0;  l2 += 1; continue; }
            else if (l2 > b2) { d0 = 1;  d1 = 0;  l2 -= 1; continue; }
            int m1 = (l1 == 7) ? 0 : ((l1 > 7) ? -1 : 1);
            int m2 = (l2 == 7) ? 0 : ((l2 > 7) ? -1 : 1);
            int A  = (l1 > 7) ? l1 - 7 : 7 - l1;
            int B  = (l2 > 7) ? l2 - 7 : 7 - l2;
            int s1v, s2v;
            if (A > B)      { s1v = (l1+m1)*IMG + l2;      s2v = (l1+m1)*IMG + l2 + m2; }
            else if (A < B) { s1v = l1*IMG + l2 + m2;      s2v = (l1+m1)*IMG + l2 + m2; }
            else            { s1v = s2v = (l1+m1)*IMG + l2 + m2; }
            g_tgt[n] = (short)(l1*IMG + l2);
            g_s1[n]  = (short)s1v;
            g_s2[n]  = (short)s2v;
            n++;
        }
    }
}

// ---------------------------------------------------------------------------
// Sinusoidal positional table (double precision to match numpy float64)
// ---------------------------------------------------------------------------
__global__ void pos_kernel() {
    int i = blockIdx.x * blockDim.x + threadIdx.x;
    if (i >= TOKENS * DIM) return;
    int p = i >> 9, j = i & 511;
    double expo = (double)(2 * (j >> 1)) / (double)DIM;
    double ang  = (double)p / pow(10000.0, expo);
    d_pos[i] = (float)((j & 1) ? cos(ang) : sin(ang));
}

// ---------------------------------------------------------------------------
// Spiral preprocessing + gather of outer ring -> tok [B*56, 256]
// One block = one image b, 32 channels. Rings applied in order; within a
// ring all reads hit already-final inner-ring cells.
// ---------------------------------------------------------------------------
__global__ __launch_bounds__(256) void spiral_kernel(const float* __restrict__ x) {
    __shared__ float s[32 * NPIX];          // 28.8 KB
    int b  = blockIdx.x >> 3;
    int cg = blockIdx.x & 7;                // channel group (32 channels)
    int tid = threadIdx.x;

    const float* src = x + ((size_t)b * CH + (size_t)cg * 32) * NPIX;
    for (int t = tid; t < 32 * NPIX; t += 256) s[t] = src[t];
    __syncthreads();

    int off = 0;
    for (int ri = 1; ri <= 7; ri++) {
        int cnt = 8 * ri;
        for (int t = tid; t < 32 * cnt; t += 256) {
            int row = t / cnt;
            int j   = t - row * cnt;
            int k   = off + j;
            float* rs = s + row * NPIX;
            rs[g_tgt[k]] += (rs[g_s1[k]] + rs[g_s2[k]]) * 0.25f;   // ratio/2
        }
        off += cnt;
        __syncthreads();
    }
    // outer-ring targets live at table indices [168, 224)
    for (int t = tid; t < NPATCH * 32; t += 256) {
        int p = t >> 5, c = t & 31;
        d_tok[((size_t)b * NPATCH + p) * CH + cg * 32 + c] = s[c * NPIX + g_tgt[168 + p]];
    }
}

// ---------------------------------------------------------------------------
// cls row assembly: h[b,0,:] = cls + pos[0,:]
// ---------------------------------------------------------------------------
__global__ void cls_kernel(const float* __restrict__ cls) {
    int i = blockIdx.x * blockDim.x + threadIdx.x;
    if (i >= BATCH * DIM) return;
    int b = i >> 9, c = i & 511;
    d_h[(size_t)b * TOKENS * DIM + c] = cls[c] + d_pos[c];
}

// ---------------------------------------------------------------------------
// SGEMM: C[M,N] = A[M,K] @ B[K,N] with fused epilogues.
// 128x128 tile, BK=16, 256 threads, 8x8 per thread. All dims tile-divisible.
// ---------------------------------------------------------------------------
#define MODE_PLAIN    0
#define MODE_EMBED    1
#define MODE_RESBIAS  2
#define MODE_BIASGELU 3

__device__ __forceinline__ float gelu_f(float v) {
    return 0.5f * v * (1.0f + erff(v * 0.7071067811865476f));
}

template<int MODE>
__global__ __launch_bounds__(256) void sgemm_kernel(
    const float* __restrict__ A, const float* __restrict__ B,
    float* C, const float* __restrict__ bias,
    const float* res, const float* __restrict__ pos,
    int M, int N, int K)
{
    __shared__ float As[16][128];
    __shared__ float Bs[16][128];

    int tid  = threadIdx.x;
    int brow = blockIdx.y * 128;
    int bcol = blockIdx.x * 128;

    int aRow = tid >> 1;            // 0..127
    int aK4  = (tid & 1) * 2;       // float4 slot 0 or 2
    int bRow = tid >> 4;            // 0..15
    int bC4  = (tid & 15) * 2;      // float4 slots

    int rb = (tid >> 4) * 8;
    int cb = (tid & 15) * 8;

    float acc[8][8];
    #pragma unroll
    for (int i = 0; i < 8; i++)
        #pragma unroll
        for (int j = 0; j < 8; j++) acc[i][j] = 0.0f;

    const float* Abase = A + (size_t)(brow + aRow) * K;
    for (int kt = 0; kt < K; kt += 16) {
        float4 a0 = *reinterpret_cast<const float4*>(Abase + kt + aK4 * 4);
        float4 a1 = *reinterpret_cast<const float4*>(Abase + kt + aK4 * 4 + 4);
        const float* Bbase = B + (size_t)(kt + bRow) * N + bcol;
        float4 b0 = reinterpret_cast<const float4*>(Bbase)[bC4];
        float4 b1 = reinterpret_cast<const float4*>(Bbase)[bC4 + 1];

        As[aK4*4+0][aRow] = a0.x; As[aK4*4+1][aRow] = a0.y;
        As[aK4*4+2][aRow] = a0.z; As[aK4*4+3][aRow] = a0.w;
        As[aK4*4+4][aRow] = a1.x; As[aK4*4+5][aRow] = a1.y;
        As[aK4*4+6][aRow] = a1.z; As[aK4*4+7][aRow] = a1.w;
        reinterpret_cast<float4*>(&Bs[bRow][0])[bC4]     = b0;
        reinterpret_cast<float4*>(&Bs[bRow][0])[bC4 + 1] = b1;
        __syncthreads();

        #pragma unroll
        for (int kk = 0; kk < 16; kk++) {
            float ar[8], br[8];
            *reinterpret_cast<float4*>(&ar[0]) = *reinterpret_cast<const float4*>(&As[kk][rb]);
            *reinterpret_cast<float4*>(&ar[4]) = *reinterpret_cast<const float4*>(&As[kk][rb + 4]);
            *reinterpret_cast<float4*>(&br[0]) = *reinterpret_cast<const float4*>(&Bs[kk][cb]);
            *reinterpret_cast<float4*>(&br[4]) = *reinterpret_cast<const float4*>(&Bs[kk][cb + 4]);
            #pragma unroll
            for (int i = 0; i < 8; i++)
                #pragma unroll
                for (int j = 0; j < 8; j++)
                    acc[i][j] = fmaf(ar[i], br[j], acc[i][j]);
        }
        __syncthreads();
    }

    #pragma unroll
    for (int i = 0; i < 8; i++) {
        int r    = brow + rb + i;
        int col0 = bcol + cb;
        float o[8];
        if (MODE == MODE_PLAIN) {
            #pragma unroll
            for (int j = 0; j < 8; j++) o[j] = acc[i][j];
            float4* cp = reinterpret_cast<float4*>(C + (size_t)r * N + col0);
            cp[0] = make_float4(o[0], o[1], o[2], o[3]);
            cp[1] = make_float4(o[4], o[5], o[6], o[7]);
        } else if (MODE == MODE_BIASGELU) {
            #pragma unroll
            for (int j = 0; j < 8; j++) o[j] = gelu_f(acc[i][j] + bias[col0 + j]);
            float4* cp = reinterpret_cast<float4*>(C + (size_t)r * N + col0);
            cp[0] = make_float4(o[0], o[1], o[2], o[3]);
            cp[1] = make_float4(o[4], o[5], o[6], o[7]);
        } else if (MODE == MODE_RESBIAS) {
            const float* rp = res + (size_t)r * N + col0;
            #pragma unroll
            for (int j = 0; j < 8; j++) o[j] = rp[j] + bias[col0 + j] + acc[i][j];
            float4* cp = reinterpret_cast<float4*>(C + (size_t)r * N + col0);
            cp[0] = make_float4(o[0], o[1], o[2], o[3]);
            cp[1] = make_float4(o[4], o[5], o[6], o[7]);
        } else { // MODE_EMBED: remap patch row r=(b*56+p) -> h row (b*57+p+1), add be + pos
            int bi = r / NPATCH;
            int p  = r - bi * NPATCH;
            const float* pr = pos + (size_t)(p + 1) * DIM + col0;
            #pragma unroll
            for (int j = 0; j < 8; j++) o[j] = acc[i][j] + bias[col0 + j] + pr[j];
            float4* cp = reinterpret_cast<float4*>(C + ((size_t)bi * TOKENS + p + 1) * DIM + col0);
            cp[0] = make_float4(o[0], o[1], o[2], o[3]);
            cp[1] = make_float4(o[4], o[5], o[6], o[7]);
        }
    }
}

// ---------------------------------------------------------------------------
// LayerNorm over last dim (512). One block (128 threads) per row.
// ---------------------------------------------------------------------------
__global__ __launch_bounds__(128) void ln_kernel(
    const float* __restrict__ X, float* __restrict__ Y,
    const float* __restrict__ g, const float* __restrict__ bta)
{
    int row = blockIdx.x;
    int tid = threadIdx.x;
    const float4* xr = reinterpret_cast<const float4*>(X + (size_t)row * DIM);
    float4 v = xr[tid];

    __shared__ float sm1[4], sm2[4];
    int w = tid >> 5, lane = tid & 31;

    float s = v.x + v.y + v.z + v.w;
    #pragma unroll
    for (int o = 16; o; o >>= 1) s += __shfl_xor_sync(0xffffffffu, s, o);
    if (lane == 0) sm1[w] = s;
    __syncthreads();
    float mu = (sm1[0] + sm1[1] + sm1[2] + sm1[3]) * (1.0f / DIM);

    float dx = v.x - mu, dy = v.y - mu, dz = v.z - mu, dw = v.w - mu;
    float q = dx*dx + dy*dy + dz*dz + dw*dw;
    #pragma unroll
    for (int o = 16; o; o >>= 1) q += __shfl_xor_sync(0xffffffffu, q, o);
    if (lane == 0) sm2[w] = q;
    __syncthreads();
    float var = (sm2[0] + sm2[1] + sm2[2] + sm2[3]) * (1.0f / DIM);
    float inv = rsqrtf(var + 1e-5f);

    float4 gg = reinterpret_cast<const float4*>(g)[tid];
    float4 bb = reinterpret_cast<const float4*>(bta)[tid];
    float4 o4 = make_float4(dx*inv*gg.x + bb.x, dy*inv*gg.y + bb.y,
                            dz*inv*gg.z + bb.z, dw*inv*gg.w + bb.w);
    reinterpret_cast<float4*>(Y + (size_t)row * DIM)[tid] = o4;
}

// ---------------------------------------------------------------------------
// Attention: one block per (b, head). 57x57 scores, softmax, @v.
// ---------------------------------------------------------------------------
__global__ __launch_bounds__(64) void attn_kernel() {
    __shared__ float ks[TOKENS][DH];
    __shared__ float vs[TOKENS][DH];
    __shared__ float sc[TOKENS][TOKENS];   // stride 57 (odd) -> conflict-free

    int b   = blockIdx.x >> 3;
    int hd  = blockIdx.x & 7;
    int tid = threadIdx.x;

    const float* base = d_qkv + (size_t)b * TOKENS * (3*DIM) + hd * DH;
    for (int t = tid; t < TOKENS * DH; t += 64) {
        int r = t >> 6, c = t & 63;
        const float* rp = base + (size_t)r * (3*DIM);
        ks[r][c] = rp[DIM + c];
        vs[r][c] = rp[2*DIM + c];
    }
    __syncthreads();

    if (tid < TOKENS) {
        float q[DH];
        const float* qp = base + (size_t)tid * (3*DIM);
        #pragma unroll
        for (int d = 0; d < DH; d++) q[d] = qp[d];

        float mx = -3.4e38f;
        for (int j = 0; j < TOKENS; j++) {
            float s = 0.0f;
            #pragma unroll
            for (int d = 0; d < DH; d++) s = fmaf(q[d], ks[j][d], s);
            s *= 0.125f;                      // DH^-0.5
            sc[tid][j] = s;
            mx = fmaxf(mx, s);
        }
        float ssum = 0.0f;
        for (int j = 0; j < TOKENS; j++) {
            float e = expf(sc[tid][j] - mx);
            sc[tid][j] = e;
            ssum += e;
        }
        float inv = 1.0f / ssum;

        float* op = d_att + ((size_t)b * TOKENS + tid) * DIM + hd * DH;
        #pragma unroll 4
        for (int d = 0; d < DH; d++) {
            float a = 0.0f;
            for (int j = 0; j < TOKENS; j++) a = fmaf(sc[tid][j], vs[j][d], a);
            op[d] = a * inv;
        }
    }
}

// ---------------------------------------------------------------------------
// Mean pool over tokens + final LN + classifier head. One block per b.
// ---------------------------------------------------------------------------
__global__ __launch_bounds__(512) void head_kernel(
    const float* __restrict__ g, const float* __restrict__ bta,
    const float* __restrict__ Wh, const float* __restrict__ bh,
    float* __restrict__ out)
{
    int b = blockIdx.x, c = threadIdx.x;
    const float* hb = d_h + (size_t)b * TOKENS * DIM;
    float s = 0.0f;
    for (int t = 0; t < TOKENS; t++) s += hb[(size_t)t * DIM + c];
    float p = s * (1.0f / (float)TOKENS);

    __shared__ float red[16];
    __shared__ float sp[DIM];
    int lane = c & 31, w = c >> 5;

    float r = p;
    #pragma unroll
    for (int o = 16; o; o >>= 1) r += __shfl_xor_sync(0xffffffffu, r, o);
    if (lane == 0) red[w] = r;
    __syncthreads();
    float mu = 0.0f;
    #pragma unroll
    for (int i = 0; i < 16; i++) mu += red[i];
    mu *= (1.0f / DIM);
    __syncthreads();

    float d = p - mu;
    r = d * d;
    #pragma unroll
    for (int o = 16; o; o >>= 1) r += __shfl_xor_sync(0xffffffffu, r, o);
    if (lane == 0) red[w] = r;
    __syncthreads();
    float var = 0.0f;
    #pragma unroll
    for (int i = 0; i < 16; i++) var += red[i];
    var *= (1.0f / DIM);
    float inv = rsqrtf(var + 1e-5f);

    sp[c] = d * inv * g[c] + bta[c];
    __syncthreads();

    // warp w computes class w (16 warps = 16 classes)
    float acc = 0.0f;
    for (int i = lane; i < DIM; i += 32) acc = fmaf(sp[i], Wh[i * NCLS + w], acc);
    #pragma unroll
    for (int o = 16; o; o >>= 1) acc += __shfl_xor_sync(0xffffffffu, acc, o);
    if (lane == 0) out[b * NCLS + w] = acc + bh[w];
}

// ---------------------------------------------------------------------------
// Launch
// ---------------------------------------------------------------------------
extern "C" void kernel_launch(void* const* d_in, const int* in_sizes, int n_in,
                              void* d_out, int out_size)
{
    (void)in_sizes; (void)n_in; (void)out_size;
    const float* x    = (const float*)d_in[0];
    const float* We   = (const float*)d_in[1];
    const float* be   = (const float*)d_in[2];
    const float* cls  = (const float*)d_in[3];
    const float* Wqkv = (const float*)d_in[4];
    const float* Wo   = (const float*)d_in[5];
    const float* bo   = (const float*)d_in[6];
    const float* ln1g = (const float*)d_in[7];
    const float* ln1b = (const float*)d_in[8];
    const float* W1   = (const float*)d_in[9];
    const float* b1   = (const float*)d_in[10];
    const float* W2   = (const float*)d_in[11];
    const float* b2   = (const float*)d_in[12];
    const float* ln2g = (const float*)d_in[13];
    const float* ln2b = (const float*)d_in[14];
    const float* lnhg = (const float*)d_in[15];
    const float* lnhb = (const float*)d_in[16];
    const float* Wh   = (const float*)d_in[17];
    const float* bh   = (const float*)d_in[18];
    float* out = (float*)d_out;

    float *tokp, *hp, *yp, *qkvp, *attp, *mlpp, *posp;
    cudaGetSymbolAddress((void**)&tokp, d_tok);
    cudaGetSymbolAddress((void**)&hp,   d_h);
    cudaGetSymbolAddress((void**)&yp,   d_y);
    cudaGetSymbolAddress((void**)&qkvp, d_qkv);
    cudaGetSymbolAddress((void**)&attp, d_att);
    cudaGetSymbolAddress((void**)&mlpp, d_mlp);
    cudaGetSymbolAddress((void**)&posp, d_pos);

    init_tables_kernel<<<1, 32>>>();
    pos_kernel<<<(TOKENS * DIM + 255) / 256, 256>>>();
    spiral_kernel<<<BATCH * 8, 256>>>(x);
    cls_kernel<<<(BATCH * DIM + 255) / 256, 256>>>(cls);

    // embed: h[:,1:,:] = tok @ We + be + pos[1:]
    sgemm_kernel<MODE_EMBED><<<dim3(DIM/128, EROWS/128), 256>>>(
        tokp, We, hp, be, nullptr, posp, EROWS, DIM, CH);

    for (int l = 0; l < DEPTH; l++) {
        ln_kernel<<<ROWS, 128>>>(hp, yp, ln1g + (size_t)l*DIM, ln1b + (size_t)l*DIM);
        sgemm_kernel<MODE_PLAIN><<<dim3(3*DIM/128, ROWS/128), 256>>>(
            yp, Wqkv + (size_t)l*DIM*3*DIM, qkvp, nullptr, nullptr, nullptr,
            ROWS, 3*DIM, DIM);
        attn_kernel<<<BATCH * HEADS, 64>>>();
        sgemm_kernel<MODE_RESBIAS><<<dim3(DIM/128, ROWS/128), 256>>>(
            attp, Wo + (size_t)l*DIM*DIM, hp, bo + (size_t)l*DIM, hp, nullptr,
            ROWS, DIM, DIM);
        ln_kernel<<<ROWS, 128>>>(hp, yp, ln2g + (size_t)l*DIM, ln2b + (size_t)l*DIM);
        sgemm_kernel<MODE_BIASGELU><<<dim3(MLPD/128, ROWS/128), 256>>>(
            yp, W1 + (size_t)l*DIM*MLPD, mlpp, b1 + (size_t)l*MLPD, nullptr, nullptr,
            ROWS, MLPD, DIM);
        sgemm_kernel<MODE_RESBIAS><<<dim3(DIM/128, ROWS/128), 256>>>(
            mlpp, W2 + (size_t)l*MLPD*DIM, hp, b2 + (size_t)l*DIM, hp, nullptr,
            ROWS, DIM, MLPD);
    }

    head_kernel<<<BATCH, 512>>>(lnhg, lnhb, Wh, bh, out);
}

// round 11
// speedup vs baseline: 1.1164x; 1.1164x over previous
#include <cuda_runtime.h>
#include <cuda_bf16.h>
#include <math.h>
#include <stdint.h>

// ---------------------------------------------------------------------------
// Problem constants
// ---------------------------------------------------------------------------
#define BATCH   512
#define IMG     15
#define NPIX    (IMG*IMG)          // 225
#define CH      256
#define DIM     512
#define HEADS   8
#define DH      64
#define DEPTH   6
#define MLPD    2048
#define NCLS    16
#define NPATCH  56
#define TOKENS  57
#define ROWS    (BATCH*TOKENS)     // 29184 = 228*128
#define EROWS   (BATCH*NPATCH)     // 28672
#define K3D     (3*DIM)            // 1536
#define K3M     (3*MLPD)           // 6144

// ---------------------------------------------------------------------------
// Scratch (device globals; no runtime allocation allowed)
// ---------------------------------------------------------------------------
__device__ __align__(128) float d_tok[(size_t)EROWS * CH];
__device__ __align__(128) float d_h  [(size_t)ROWS  * DIM];
__device__ __align__(128) float d_qkv[(size_t)ROWS  * 3*DIM];
__device__ __align__(128) float d_pos[TOKENS * DIM];
__device__ short g_tgt[224], g_s1[224], g_s2[224];

// triple-packed split-bf16 activations: [hi | lo | hi] along K
__device__ __align__(128) __nv_bfloat16 d_y3[(size_t)ROWS * K3D];   // ~90MB
__device__ __align__(128) __nv_bfloat16 d_a3[(size_t)ROWS * K3D];   // ~90MB
__device__ __align__(128) __nv_bfloat16 d_m3[(size_t)ROWS * K3M];   // ~359MB

// triple-packed split-bf16 weights, transposed: [N][3K] = [hi | hi | lo]
__device__ __align__(128) __nv_bfloat16 d_wq3[(size_t)DEPTH * (3*DIM) * K3D];
__device__ __align__(128) __nv_bfloat16 d_wo3[(size_t)DEPTH * DIM * K3D];
__device__ __align__(128) __nv_bfloat16 d_w13[(size_t)DEPTH * MLPD * K3D];
__device__ __align__(128) __nv_bfloat16 d_w23[(size_t)DEPTH * DIM * K3M];

// ---------------------------------------------------------------------------
// PTX helpers (arch-neutral: cp.async + ldmatrix + mma.sync, all sm_80+)
// ---------------------------------------------------------------------------
__device__ __forceinline__ uint32_t smem_u32(const void* p) {
    uint32_t a;
    asm("{ .reg .u64 t; cvta.to.shared.u64 t, %1; cvt.u32.u64 %0, t; }"
        : "=r"(a) : "l"(p));
    return a;
}
__device__ __forceinline__ void cp_async16(uint32_t dst, const void* src) {
    asm volatile("cp.async.cg.shared.global [%0], [%1], 16;" :: "r"(dst), "l"(src));
}
#define CP_COMMIT() asm volatile("cp.async.commit_group;" ::: "memory")
#define CP_WAIT2()  asm volatile("cp.async.wait_group 2;" ::: "memory")
#define CP_WAIT0()  asm volatile("cp.async.wait_group 0;" ::: "memory")

__device__ __forceinline__ void ldm_x4(uint32_t* r, uint32_t addr) {
    asm volatile("ldmatrix.sync.aligned.m8n8.x4.shared.b16 {%0,%1,%2,%3}, [%4];"
        : "=r"(r[0]), "=r"(r[1]), "=r"(r[2]), "=r"(r[3]) : "r"(addr));
}
__device__ __forceinline__ void mma_bf16(float* c, const uint32_t* a,
                                         uint32_t b0, uint32_t b1) {
    asm volatile(
        "mma.sync.aligned.m16n8k16.row.col.f32.bf16.bf16.f32 "
        "{%0,%1,%2,%3}, {%4,%5,%6,%7}, {%8,%9}, {%0,%1,%2,%3};"
        : "+f"(c[0]), "+f"(c[1]), "+f"(c[2]), "+f"(c[3])
        : "r"(a[0]), "r"(a[1]), "r"(a[2]), "r"(a[3]), "r"(b0), "r"(b1));
}

// ---------------------------------------------------------------------------
// Ring-table init (exact replica of reference _ring traversal)
// ---------------------------------------------------------------------------
__global__ void init_tables_kernel() {
    if (threadIdx.x != 0 || blockIdx.x != 0) return;
    int n = 0;
    for (int i = 1; i <= 7; i++) {
        int a1 = 7 - i, a2 = 7 + i, b1 = 7 - i, b2 = 7 + i;
        int d0 = 0, d1 = 1, l1 = a1, l2 = b1 - 1, start = 0;
        while (true) {
            l1 += d0; l2 += d1;
            if (l1 == a1 && l2 == b1) { if (start) break; start = 1; }
            if (l1 > a2)      { d0 = 0;  d1 = -1; l1 -= 1; continue; }
            else if (l2 < b1) { d0 = -1; d1 = 0;  l2 += 1; continue; }
            else if (l2 > b2) { d0 = 1;  d1 = 0;  l2 -= 1; continue; }
            int m1 = (l1 == 7) ? 0 : ((l1 > 7) ? -1 : 1);
            int m2 = (l2 == 7) ? 0 : ((l2 > 7) ? -1 : 1);
            int A  = (l1 > 7) ? l1 - 7 : 7 - l1;
            int B  = (l2 > 7) ? l2 - 7 : 7 - l2;
            int s1v, s2v;
            if (A > B)      { s1v = (l1+m1)*IMG + l2;      s2v = (l1+m1)*IMG + l2 + m2; }
            else if (A < B) { s1v = l1*IMG + l2 + m2;      s2v = (l1+m1)*IMG + l2 + m2; }
            else            { s1v = s2v = (l1+m1)*IMG + l2 + m2; }
            g_tgt[n] = (short)(l1*IMG + l2);
            g_s1[n]  = (short)s1v;
            g_s2[n]  = (short)s2v;
            n++;
        }
    }
}

__global__ void pos_kernel() {
    int i = blockIdx.x * blockDim.x + threadIdx.x;
    if (i >= TOKENS * DIM) return;
    int p = i >> 9, j = i & 511;
    double expo = (double)(2 * (j >> 1)) / (double)DIM;
    double ang  = (double)p / pow(10000.0, expo);
    d_pos[i] = (float)((j & 1) ? cos(ang) : sin(ang));
}

// ---------------------------------------------------------------------------
// Spiral preprocessing + outer-ring gather
// ---------------------------------------------------------------------------
__global__ __launch_bounds__(256) void spiral_kernel(const float* __restrict__ x) {
    __shared__ float s[32 * NPIX];
    int b  = blockIdx.x >> 3;
    int cg = blockIdx.x & 7;
    int tid = threadIdx.x;

    const float* src = x + ((size_t)b * CH + (size_t)cg * 32) * NPIX;
    for (int t = tid; t < 32 * NPIX; t += 256) s[t] = src[t];
    __syncthreads();

    int off = 0;
    for (int ri = 1; ri <= 7; ri++) {
        int cnt = 8 * ri;
        for (int t = tid; t < 32 * cnt; t += 256) {
            int row = t / cnt;
            int j   = t - row * cnt;
            int k   = off + j;
            float* rs = s + row * NPIX;
            rs[g_tgt[k]] += (rs[g_s1[k]] + rs[g_s2[k]]) * 0.25f;
        }
        off += cnt;
        __syncthreads();
    }
    for (int t = tid; t < NPATCH * 32; t += 256) {
        int p = t >> 5, c = t & 31;
        d_tok[((size_t)b * NPATCH + p) * CH + cg * 32 + c] = s[c * NPIX + g_tgt[168 + p]];
    }
}

__global__ void cls_kernel(const float* __restrict__ cls) {
    int i = blockIdx.x * blockDim.x + threadIdx.x;
    if (i >= BATCH * DIM) return;
    int b = i >> 9, c = i & 511;
    d_h[(size_t)b * TOKENS * DIM + c] = cls[c] + d_pos[c];
}

// ---------------------------------------------------------------------------
// Weight split+transpose into triple layout:
// W[K][N] fp32 -> T3[N][3K] bf16 with [hi | hi | lo]
// ---------------------------------------------------------------------------
__global__ __launch_bounds__(256) void wsplit3_kernel(
    const float* __restrict__ W, __nv_bfloat16* __restrict__ T3, int K, int N)
{
    __shared__ float tile[32][33];
    int tx = threadIdx.x, ty = threadIdx.y;
    int n0 = blockIdx.x * 32, k0 = blockIdx.y * 32;
    #pragma unroll
    for (int j = 0; j < 32; j += 8)
        tile[ty + j][tx] = W[(size_t)(k0 + ty + j) * N + n0 + tx];
    __syncthreads();
    #pragma unroll
    for (int j = 0; j < 32; j += 8) {
        float v = tile[tx][ty + j];
        __nv_bfloat16 hi = __float2bfloat16(v);
        __nv_bfloat16 lo = __float2bfloat16(v - __bfloat162float(hi));
        size_t rb = (size_t)(n0 + ty + j) * (3 * K) + k0 + tx;
        T3[rb]         = hi;
        T3[rb + K]     = hi;
        T3[rb + 2*K]   = lo;
    }
}

// ---------------------------------------------------------------------------
// Embed GEMM (fp32): h[:,1:,:] = tok @ We + be + pos[1:]
// ---------------------------------------------------------------------------
__global__ __launch_bounds__(256) void embed_gemm_kernel(
    const float* __restrict__ A, const float* __restrict__ B,
    const float* __restrict__ bias)
{
    __shared__ float As[16][128];
    __shared__ float Bs[16][128];
    int tid  = threadIdx.x;
    int brow = blockIdx.y * 128;
    int bcol = blockIdx.x * 128;
    int aRow = tid >> 1;
    int aK4  = (tid & 1) * 2;
    int bRow = tid >> 4;
    int bC4  = (tid & 15) * 2;
    int rb = (tid >> 4) * 8;
    int cb = (tid & 15) * 8;

    float acc[8][8];
    #pragma unroll
    for (int i = 0; i < 8; i++)
        #pragma unroll
        for (int j = 0; j < 8; j++) acc[i][j] = 0.0f;

    const float* Abase = A + (size_t)(brow + aRow) * CH;
    for (int kt = 0; kt < CH; kt += 16) {
        float4 a0 = *reinterpret_cast<const float4*>(Abase + kt + aK4 * 4);
        float4 a1 = *reinterpret_cast<const float4*>(Abase + kt + aK4 * 4 + 4);
        const float* Bbase = B + (size_t)(kt + bRow) * DIM + bcol;
        float4 b0 = reinterpret_cast<const float4*>(Bbase)[bC4];
        float4 b1 = reinterpret_cast<const float4*>(Bbase)[bC4 + 1];
        As[aK4*4+0][aRow] = a0.x; As[aK4*4+1][aRow] = a0.y;
        As[aK4*4+2][aRow] = a0.z; As[aK4*4+3][aRow] = a0.w;
        As[aK4*4+4][aRow] = a1.x; As[aK4*4+5][aRow] = a1.y;
        As[aK4*4+6][aRow] = a1.z; As[aK4*4+7][aRow] = a1.w;
        reinterpret_cast<float4*>(&Bs[bRow][0])[bC4]     = b0;
        reinterpret_cast<float4*>(&Bs[bRow][0])[bC4 + 1] = b1;
        __syncthreads();
        #pragma unroll
        for (int kk = 0; kk < 16; kk++) {
            float ar[8], br[8];
            *reinterpret_cast<float4*>(&ar[0]) = *reinterpret_cast<const float4*>(&As[kk][rb]);
            *reinterpret_cast<float4*>(&ar[4]) = *reinterpret_cast<const float4*>(&As[kk][rb + 4]);
            *reinterpret_cast<float4*>(&br[0]) = *reinterpret_cast<const float4*>(&Bs[kk][cb]);
            *reinterpret_cast<float4*>(&br[4]) = *reinterpret_cast<const float4*>(&Bs[kk][cb + 4]);
            #pragma unroll
            for (int i = 0; i < 8; i++)
                #pragma unroll
                for (int j = 0; j < 8; j++)
                    acc[i][j] = fmaf(ar[i], br[j], acc[i][j]);
        }
        __syncthreads();
    }

    #pragma unroll
    for (int i = 0; i < 8; i++) {
        int r    = brow + rb + i;
        int col0 = bcol + cb;
        int bi = r / NPATCH;
        int p  = r - bi * NPATCH;
        const float* pr = d_pos + (size_t)(p + 1) * DIM + col0;
        float o[8];
        #pragma unroll
        for (int j = 0; j < 8; j++) o[j] = acc[i][j] + bias[col0 + j] + pr[j];
        float4* cp = reinterpret_cast<float4*>(d_h + ((size_t)bi * TOKENS + p + 1) * DIM + col0);
        cp[0] = make_float4(o[0], o[1], o[2], o[3]);
        cp[1] = make_float4(o[4], o[5], o[6], o[7]);
    }
}

// ---------------------------------------------------------------------------
// LayerNorm -> triple-packed split bf16 ([hi | lo | hi], row stride 1536)
// ---------------------------------------------------------------------------
__global__ __launch_bounds__(128) void ln3_kernel(
    const float* __restrict__ X, __nv_bfloat16* __restrict__ Y3,
    const float* __restrict__ g, const float* __restrict__ bta)
{
    int row = blockIdx.x;
    int tid = threadIdx.x;
    const float4* xr = reinterpret_cast<const float4*>(X + (size_t)row * DIM);
    float4 v = xr[tid];

    __shared__ float sm1[4], sm2[4];
    int w = tid >> 5, lane = tid & 31;

    float s = v.x + v.y + v.z + v.w;
    #pragma unroll
    for (int o = 16; o; o >>= 1) s += __shfl_xor_sync(0xffffffffu, s, o);
    if (lane == 0) sm1[w] = s;
    __syncthreads();
    float mu = (sm1[0] + sm1[1] + sm1[2] + sm1[3]) * (1.0f / DIM);

    float dx = v.x - mu, dy = v.y - mu, dz = v.z - mu, dw = v.w - mu;
    float q = dx*dx + dy*dy + dz*dz + dw*dw;
    #pragma unroll
    for (int o = 16; o; o >>= 1) q += __shfl_xor_sync(0xffffffffu, q, o);
    if (lane == 0) sm2[w] = q;
    __syncthreads();
    float var = (sm2[0] + sm2[1] + sm2[2] + sm2[3]) * (1.0f / DIM);
    float inv = rsqrtf(var + 1e-5f);

    float4 gg = reinterpret_cast<const float4*>(g)[tid];
    float4 bb = reinterpret_cast<const float4*>(bta)[tid];
    float o0 = dx*inv*gg.x + bb.x, o1 = dy*inv*gg.y + bb.y;
    float o2 = dz*inv*gg.z + bb.z, o3 = dw*inv*gg.w + bb.w;

    __nv_bfloat16 h0 = __float2bfloat16(o0), h1 = __float2bfloat16(o1);
    __nv_bfloat16 h2 = __float2bfloat16(o2), h3 = __float2bfloat16(o3);
    __nv_bfloat162 hhA{h0, h1}, hhB{h2, h3};
    __nv_bfloat162 llA{__float2bfloat16(o0 - __bfloat162float(h0)),
                       __float2bfloat16(o1 - __bfloat162float(h1))};
    __nv_bfloat162 llB{__float2bfloat16(o2 - __bfloat162float(h2)),
                       __float2bfloat16(o3 - __bfloat162float(h3))};

    size_t o = (size_t)row * K3D + tid * 4;
    __nv_bfloat162* p0 = reinterpret_cast<__nv_bfloat162*>(Y3 + o);
    __nv_bfloat162* p1 = reinterpret_cast<__nv_bfloat162*>(Y3 + o + DIM);
    __nv_bfloat162* p2 = reinterpret_cast<__nv_bfloat162*>(Y3 + o + 2*DIM);
    p0[0] = hhA; p0[1] = hhB;
    p1[0] = llA; p1[1] = llB;
    p2[0] = hhA; p2[1] = hhB;
}

// ---------------------------------------------------------------------------
// Attention: one block per (b, head); writes triple-packed split output
// ---------------------------------------------------------------------------
__global__ __launch_bounds__(64) void attn_kernel() {
    __shared__ float ks[TOKENS][DH];
    __shared__ float vs[TOKENS][DH];
    __shared__ float sc[TOKENS][TOKENS];

    int b   = blockIdx.x >> 3;
    int hd  = blockIdx.x & 7;
    int tid = threadIdx.x;

    const float* base = d_qkv + (size_t)b * TOKENS * (3*DIM) + hd * DH;
    for (int t = tid; t < TOKENS * DH; t += 64) {
        int r = t >> 6, c = t & 63;
        const float* rp = base + (size_t)r * (3*DIM);
        ks[r][c] = rp[DIM + c];
        vs[r][c] = rp[2*DIM + c];
    }
    __syncthreads();

    if (tid < TOKENS) {
        float q[DH];
        const float* qp = base + (size_t)tid * (3*DIM);
        #pragma unroll
        for (int d = 0; d < DH; d++) q[d] = qp[d];

        float mx = -3.4e38f;
        for (int j = 0; j < TOKENS; j++) {
            float s = 0.0f;
            #pragma unroll
            for (int d = 0; d < DH; d++) s = fmaf(q[d], ks[j][d], s);
            s *= 0.125f;
            sc[tid][j] = s;
            mx = fmaxf(mx, s);
        }
        float ssum = 0.0f;
        for (int j = 0; j < TOKENS; j++) {
            float e = expf(sc[tid][j] - mx);
            sc[tid][j] = e;
            ssum += e;
        }
        float inv = 1.0f / ssum;

        size_t ob = ((size_t)b * TOKENS + tid) * K3D + hd * DH;
        #pragma unroll 4
        for (int d = 0; d < DH; d++) {
            float a = 0.0f;
            for (int j = 0; j < TOKENS; j++) a = fmaf(sc[tid][j], vs[j][d], a);
            float v = a * inv;
            __nv_bfloat16 hi = __float2bfloat16(v);
            __nv_bfloat16 lo = __float2bfloat16(v - __bfloat162float(hi));
            d_a3[ob + d]         = hi;
            d_a3[ob + DIM + d]   = lo;
            d_a3[ob + 2*DIM + d] = hi;
        }
    }
}

// ---------------------------------------------------------------------------
// bf16 HMMA GEMM via mma.sync: C[M,N] = A3[M,K3] @ B3[N,K3]^T
// 128x128x32 tiles, 4-stage cp.async, 8 warps (2x4) of 64x32 warp tiles.
// smem rows padded to 80B -> conflict-free ldmatrix.
// ---------------------------------------------------------------------------
#define GM_PLAIN  0
#define GM_RESBIAS 1
#define GM_GELU3  2

#define HG_STAGE  20480                   // A 10240 + B 10240
#define HG_SMEM   (4 * HG_STAGE)          // 81920

__device__ __forceinline__ float gelu_f(float v) {
    return 0.5f * v * (1.0f + erff(v * 0.7071067811865476f));
}

template<int MODE>
__global__ void __launch_bounds__(256, 2) hgemm_kernel(
    const __nv_bfloat16* __restrict__ A, const __nv_bfloat16* __restrict__ B,
    float* __restrict__ Cf, const float* __restrict__ bias,
    __nv_bfloat16* __restrict__ O3,
    int K3, int ldC)
{
    extern __shared__ char sm[];
    const int tid = threadIdx.x;
    const int m0 = blockIdx.y * 128;
    const int n0 = blockIdx.x * 128;
    const uint32_t sbase = smem_u32(sm);

    const int nk = K3 >> 5;   // BK = 32

    // --- async stage loader: 512 x 16B per operand, 2 iters per thread ---
    auto load_stage = [&](int kt, int s) {
        uint32_t st = sbase + s * HG_STAGE;
        int k0 = kt << 5;
        #pragma unroll
        for (int j = 0; j < 2; j++) {
            int idx = tid + j * 256;          // 0..511
            int row = idx >> 2, ch = idx & 3; // 4 x 16B chunks per 64B row
            cp_async16(st + row * 80 + ch * 16,
                       A + (size_t)(m0 + row) * K3 + k0 + ch * 8);
            cp_async16(st + 10240 + row * 80 + ch * 16,
                       B + (size_t)(n0 + row) * K3 + k0 + ch * 8);
        }
        CP_COMMIT();
    };

    #pragma unroll
    for (int s = 0; s < 3; s++) load_stage(s, s);

    const int w = tid >> 5, lane = tid & 31;
    const int wm = w >> 2, wn = w & 3;        // 2 x 4 warp grid

    float acc[4][4][4];
    #pragma unroll
    for (int mt = 0; mt < 4; mt++)
        #pragma unroll
        for (int nt = 0; nt < 4; nt++)
            #pragma unroll
            for (int i = 0; i < 4; i++) acc[mt][nt][i] = 0.0f;

    // per-lane ldmatrix address components (constant across stages)
    const int arow_off = lane & 15;                 // A: rows within 16
    const int akb_off  = (lane >> 4) << 3;          // A: +8 k for lanes 16-31
    const int brow_off = (lane & 7) | ((lane >> 4) << 3);  // B: n within 16
    const int bkb_off  = ((lane >> 3) & 1) << 3;    // B: +8 k for lanes 8-15,24-31

    for (int kt = 0; kt < nk; kt++) {
        CP_WAIT2();
        __syncthreads();
        if (kt + 3 < nk) load_stage(kt + 3, (kt + 3) & 3);
        else             CP_COMMIT();

        uint32_t sa = sbase + (kt & 3) * HG_STAGE;
        uint32_t sb = sa + 10240;

        #pragma unroll
        for (int kk = 0; kk < 2; kk++) {
            uint32_t af[4][4];
            #pragma unroll
            for (int mt = 0; mt < 4; mt++) {
                int r  = wm * 64 + mt * 16 + arow_off;
                int kb = kk * 16 + akb_off;
                ldm_x4(af[mt], sa + r * 80 + (kb >> 3) * 16);
            }
            uint32_t bfr[2][4];
            #pragma unroll
            for (int np = 0; np < 2; np++) {
                int r  = wn * 32 + np * 16 + brow_off;
                int kb = kk * 16 + bkb_off;
                ldm_x4(bfr[np], sb + r * 80 + (kb >> 3) * 16);
            }
            #pragma unroll
            for (int mt = 0; mt < 4; mt++)
                #pragma unroll
                for (int nt = 0; nt < 4; nt++) {
                    int np = nt >> 1, hb = (nt & 1) * 2;
                    mma_bf16(acc[mt][nt], af[mt], bfr[np][hb], bfr[np][hb + 1]);
                }
        }
        __syncthreads();
    }
    CP_WAIT0();

    // --- epilogue ---
    const int qr = lane >> 2, qc = (lane & 3) * 2;
    #pragma unroll
    for (int mt = 0; mt < 4; mt++) {
        #pragma unroll
        for (int rr = 0; rr < 2; rr++) {
            int row = m0 + wm * 64 + mt * 16 + qr + rr * 8;
            #pragma unroll
            for (int nt = 0; nt < 4; nt++) {
                int col = n0 + wn * 32 + nt * 8 + qc;
                float v0 = acc[mt][nt][rr * 2 + 0];
                float v1 = acc[mt][nt][rr * 2 + 1];
                if (MODE == GM_PLAIN) {
                    float2* cp = reinterpret_cast<float2*>(Cf + (size_t)row * ldC + col);
                    *cp = make_float2(v0, v1);
                } else if (MODE == GM_RESBIAS) {
                    float2* cp = reinterpret_cast<float2*>(Cf + (size_t)row * ldC + col);
                    float2 c = *cp;
                    c.x = c.x + bias[col]     + v0;
                    c.y = c.y + bias[col + 1] + v1;
                    *cp = c;
                } else { // GM_GELU3: bias + gelu, resplit into [hi | lo | hi], N=2048
                    float g0 = gelu_f(v0 + bias[col]);
                    float g1 = gelu_f(v1 + bias[col + 1]);
                    __nv_bfloat16 h0 = __float2bfloat16(g0);
                    __nv_bfloat16 h1 = __float2bfloat16(g1);
                    __nv_bfloat162 hh{h0, h1};
                    __nv_bfloat162 ll{__float2bfloat16(g0 - __bfloat162float(h0)),
                                      __float2bfloat16(g1 - __bfloat162float(h1))};
                    size_t rb = (size_t)row * K3M + col;
                    *reinterpret_cast<__nv_bfloat162*>(O3 + rb)            = hh;
                    *reinterpret_cast<__nv_bfloat162*>(O3 + rb + MLPD)     = ll;
                    *reinterpret_cast<__nv_bfloat162*>(O3 + rb + 2*MLPD)   = hh;
                }
            }
        }
    }
}

// ---------------------------------------------------------------------------
// Head: mean pool + LN + classifier
// ---------------------------------------------------------------------------
__global__ __launch_bounds__(512) void head_kernel(
    const float* __restrict__ g, const float* __restrict__ bta,
    const float* __restrict__ Wh, const float* __restrict__ bh,
    float* __restrict__ out)
{
    int b = blockIdx.x, c = threadIdx.x;
    const float* hb = d_h + (size_t)b * TOKENS * DIM;
    float s = 0.0f;
    for (int t = 0; t < TOKENS; t++) s += hb[(size_t)t * DIM + c];
    float p = s * (1.0f / (float)TOKENS);

    __shared__ float red[16];
    __shared__ float sp[DIM];
    int lane = c & 31, w = c >> 5;

    float r = p;
    #pragma unroll
    for (int o = 16; o; o >>= 1) r += __shfl_xor_sync(0xffffffffu, r, o);
    if (lane == 0) red[w] = r;
    __syncthreads();
    float mu = 0.0f;
    #pragma unroll
    for (int i = 0; i < 16; i++) mu += red[i];
    mu *= (1.0f / DIM);
    __syncthreads();

    float d = p - mu;
    r = d * d;
    #pragma unroll
    for (int o = 16; o; o >>= 1) r += __shfl_xor_sync(0xffffffffu, r, o);
    if (lane == 0) red[w] = r;
    __syncthreads();
    float var = 0.0f;
    #pragma unroll
    for (int i = 0; i < 16; i++) var += red[i];
    var *= (1.0f / DIM);
    float inv = rsqrtf(var + 1e-5f);

    sp[c] = d * inv * g[c] + bta[c];
    __syncthreads();

    float acc = 0.0f;
    for (int i = lane; i < DIM; i += 32) acc = fmaf(sp[i], Wh[i * NCLS + w], acc);
    #pragma unroll
    for (int o = 16; o; o >>= 1) acc += __shfl_xor_sync(0xffffffffu, acc, o);
    if (lane == 0) out[b * NCLS + w] = acc + bh[w];
}

// ---------------------------------------------------------------------------
// Launch
// ---------------------------------------------------------------------------
extern "C" void kernel_launch(void* const* d_in, const int* in_sizes, int n_in,
                              void* d_out, int out_size)
{
    (void)in_sizes; (void)n_in; (void)out_size;
    const float* x    = (const float*)d_in[0];
    const float* We   = (const float*)d_in[1];
    const float* be   = (const float*)d_in[2];
    const float* cls  = (const float*)d_in[3];
    const float* Wqkv = (const float*)d_in[4];
    const float* Wo   = (const float*)d_in[5];
    const float* bo   = (const float*)d_in[6];
    const float* ln1g = (const float*)d_in[7];
    const float* ln1b = (const float*)d_in[8];
    const float* W1   = (const float*)d_in[9];
    const float* b1   = (const float*)d_in[10];
    const float* W2   = (const float*)d_in[11];
    const float* b2   = (const float*)d_in[12];
    const float* ln2g = (const float*)d_in[13];
    const float* ln2b = (const float*)d_in[14];
    const float* lnhg = (const float*)d_in[15];
    const float* lnhb = (const float*)d_in[16];
    const float* Wh   = (const float*)d_in[17];
    const float* bh   = (const float*)d_in[18];
    float* out = (float*)d_out;

    float *tokp, *hp, *qkvp;
    __nv_bfloat16 *y3, *a3, *m3, *wq3, *wo3, *w13, *w23;
    cudaGetSymbolAddress((void**)&tokp, d_tok);
    cudaGetSymbolAddress((void**)&hp,   d_h);
    cudaGetSymbolAddress((void**)&qkvp, d_qkv);
    cudaGetSymbolAddress((void**)&y3,  d_y3);
    cudaGetSymbolAddress((void**)&a3,  d_a3);
    cudaGetSymbolAddress((void**)&m3,  d_m3);
    cudaGetSymbolAddress((void**)&wq3, d_wq3);
    cudaGetSymbolAddress((void**)&wo3, d_wo3);
    cudaGetSymbolAddress((void**)&w13, d_w13);
    cudaGetSymbolAddress((void**)&w23, d_w23);

    cudaFuncSetAttribute(hgemm_kernel<GM_PLAIN>,
                         cudaFuncAttributeMaxDynamicSharedMemorySize, HG_SMEM);
    cudaFuncSetAttribute(hgemm_kernel<GM_RESBIAS>,
                         cudaFuncAttributeMaxDynamicSharedMemorySize, HG_SMEM);
    cudaFuncSetAttribute(hgemm_kernel<GM_GELU3>,
                         cudaFuncAttributeMaxDynamicSharedMemorySize, HG_SMEM);

    init_tables_kernel<<<1, 32>>>();
    pos_kernel<<<(TOKENS * DIM + 255) / 256, 256>>>();
    spiral_kernel<<<BATCH * 8, 256>>>(x);
    cls_kernel<<<(BATCH * DIM + 255) / 256, 256>>>(cls);

    // weight split+transpose into triple layout (once per launch)
    for (int l = 0; l < DEPTH; l++) {
        wsplit3_kernel<<<dim3(3*DIM/32, DIM/32), dim3(32, 8)>>>(
            Wqkv + (size_t)l*DIM*3*DIM, wq3 + (size_t)l*(3*DIM)*K3D, DIM, 3*DIM);
        wsplit3_kernel<<<dim3(DIM/32, DIM/32), dim3(32, 8)>>>(
            Wo + (size_t)l*DIM*DIM, wo3 + (size_t)l*DIM*K3D, DIM, DIM);
        wsplit3_kernel<<<dim3(MLPD/32, DIM/32), dim3(32, 8)>>>(
            W1 + (size_t)l*DIM*MLPD, w13 + (size_t)l*MLPD*K3D, DIM, MLPD);
        wsplit3_kernel<<<dim3(DIM/32, MLPD/32), dim3(32, 8)>>>(
            W2 + (size_t)l*MLPD*DIM, w23 + (size_t)l*DIM*K3M, MLPD, DIM);
    }

    embed_gemm_kernel<<<dim3(DIM/128, EROWS/128), 256>>>(tokp, We, be);

    for (int l = 0; l < DEPTH; l++) {
        ln3_kernel<<<ROWS, 128>>>(hp, y3, ln1g + (size_t)l*DIM, ln1b + (size_t)l*DIM);
        hgemm_kernel<GM_PLAIN><<<dim3(3*DIM/128, ROWS/128), 256, HG_SMEM>>>(
            y3, wq3 + (size_t)l*(3*DIM)*K3D, qkvp, nullptr, nullptr, K3D, 3*DIM);
        attn_kernel<<<BATCH * HEADS, 64>>>();
        hgemm_kernel<GM_RESBIAS><<<dim3(DIM/128, ROWS/128), 256, HG_SMEM>>>(
            a3, wo3 + (size_t)l*DIM*K3D, hp, bo + (size_t)l*DIM, nullptr, K3D, DIM);
        ln3_kernel<<<ROWS, 128>>>(hp, y3, ln2g + (size_t)l*DIM, ln2b + (size_t)l*DIM);
        hgemm_kernel<GM_GELU3><<<dim3(MLPD/128, ROWS/128), 256, HG_SMEM>>>(
            y3, w13 + (size_t)l*MLPD*K3D, nullptr, b1 + (size_t)l*MLPD, m3, K3D, MLPD);
        hgemm_kernel<GM_RESBIAS><<<dim3(DIM/128, ROWS/128), 256, HG_SMEM>>>(
            m3, w23 + (size_t)l*DIM*K3M, hp, b2 + (size_t)l*DIM, nullptr, K3M, DIM);
    }

    head_kernel<<<BATCH, 512>>>(lnhg, lnhb, Wh, bh, out);
}